// round 5
// baseline (speedup 1.0000x reference)
#include <cuda_runtime.h>
#include <math.h>

#define D 128
#define NN 8192
#define NE 16384
#define NS 4096
#define NG 256
#define OPS 105
#define NSTEPS 12

typedef unsigned long long ull;

// ---------------- scratch (device globals; no runtime allocation) ----------
__device__ float d_h[NN*D], d_agg[NN*D], d_m[NN*D];
__device__ float d_gi[NN*3*D], d_gh[NN*3*D];
__device__ float d_sg[NS*D], d_se[NS*D], d_s1[NS*D];
__device__ float d_gm[NG*D], d_g1[NG*D];
__device__ int   d_deg[NN], d_off[NN+1], d_cur[NN], d_csr[NE];
__device__ float d_invdeg[NN];

// ---------------- helpers ----------------
__device__ __forceinline__ ull pack2(float x){unsigned u=__float_as_uint(x);ull r;asm("mov.b64 %0,{%1,%1};":"=l"(r):"r"(u));return r;}
__device__ __forceinline__ void fma2(ull&a,ull x,ull y){asm("fma.rn.f32x2 %0,%1,%2,%0;":"+l"(a):"l"(x),"l"(y));}
__device__ __forceinline__ float lo32(ull v){return __uint_as_float((unsigned)v);}
__device__ __forceinline__ float hi32(ull v){return __uint_as_float((unsigned)(v>>32));}
__device__ __forceinline__ float lrelu(float v){return v>0.f?v:0.01f*v;}

// ---------------- CSR build ----------------
__global__ void k_zero(){int i=blockIdx.x*blockDim.x+threadIdx.x;if(i<NN)d_deg[i]=0;}
__global__ void k_count(const int* __restrict__ ei){int e=blockIdx.x*blockDim.x+threadIdx.x;if(e<NE)atomicAdd(&d_deg[ei[NE+e]],1);}
__global__ void k_scan(){ // 1 block, 1024 threads, 8 elems each -> exclusive scan of deg
    __shared__ int ws[32];
    int t=threadIdx.x,base=t*8,v[8],pre[8],s=0;
#pragma unroll
    for(int i=0;i<8;i++){v[i]=d_deg[base+i];pre[i]=s;s+=v[i];}
    int lane=t&31,wid=t>>5,x=s;
#pragma unroll
    for(int o=1;o<32;o<<=1){int y=__shfl_up_sync(~0u,x,o);if(lane>=o)x+=y;}
    if(lane==31)ws[wid]=x;
    __syncthreads();
    if(wid==0){int w=ws[lane],xx=w;
#pragma unroll
        for(int o=1;o<32;o<<=1){int y=__shfl_up_sync(~0u,xx,o);if(lane>=o)xx+=y;}
        ws[lane]=xx-w;}
    __syncthreads();
    int obase=ws[wid]+(x-s);
#pragma unroll
    for(int i=0;i<8;i++){int o=obase+pre[i];d_off[base+i]=o;d_cur[base+i]=o;
        d_invdeg[base+i]=v[i]>0?1.0f/(float)v[i]:0.0f;}
    if(t==1023)d_off[NN]=obase+s;
}
__global__ void k_fill(const int* __restrict__ ei){int e=blockIdx.x*blockDim.x+threadIdx.x;
    if(e<NE){int p=atomicAdd(&d_cur[ei[NE+e]],1);d_csr[p]=e;}}
__global__ void k_sortl(){ // per-node insertion sort -> deterministic float sums
    int n=blockIdx.x*blockDim.x+threadIdx.x;if(n>=NN)return;
    int a=d_off[n],b=d_off[n+1];
    for(int i=a+1;i<b;i++){int key=d_csr[i],j=i-1;
        while(j>=a&&d_csr[j]>key){d_csr[j+1]=d_csr[j];j--;}d_csr[j+1]=key;}
}

// ---------------- generic GEMM: C[M x N] = A[M x128] @ (W or W^T) (+add)(+bias)(act) ---
// block: 256 thr, tile 64 rows x 128 cols. transW: W is [N][ldw] row-major (use W[j][k]).
__global__ void __launch_bounds__(256)
k_gemm(const float* __restrict__ A,const float* __restrict__ W,
       const float* __restrict__ bias,const float* __restrict__ add,int ldadd,
       float* __restrict__ C,int ldc,int N,int ldw,int transW,int act){
    __shared__ float At[32*68];   // [k][row], stride 68
    __shared__ float Bp[32*128];  // [k][col]
    int t=threadIdx.x,rg=t>>5,cg=t&31;
    int row0=blockIdx.x*64,jt=blockIdx.y*128;
    ull acc[4][4];
#pragma unroll
    for(int p=0;p<4;p++)
#pragma unroll
        for(int c=0;c<4;c++)acc[p][c]=0ull;
    for(int kc=0;kc<128;kc+=32){
        { int rl=t&63,kg=t>>6;const float*src=A+(row0+rl)*128+kc+kg*8;
          float4 v0=*(const float4*)src,v1=*(const float4*)(src+4);int kb=kg*8;
          At[(kb+0)*68+rl]=v0.x;At[(kb+1)*68+rl]=v0.y;At[(kb+2)*68+rl]=v0.z;At[(kb+3)*68+rl]=v0.w;
          At[(kb+4)*68+rl]=v1.x;At[(kb+5)*68+rl]=v1.y;At[(kb+6)*68+rl]=v1.z;At[(kb+7)*68+rl]=v1.w;}
        if(transW){
            int j=t>>1,h=t&1;
            if(jt+j<N){const float*src=W+(jt+j)*ldw+kc+h*16;
#pragma unroll
                for(int i=0;i<4;i++){float4 v=*(const float4*)(src+i*4);int kk=h*16+i*4;
                    Bp[(kk+0)*128+j]=v.x;Bp[(kk+1)*128+j]=v.y;Bp[(kk+2)*128+j]=v.z;Bp[(kk+3)*128+j]=v.w;}
            }else{
#pragma unroll
                for(int i=0;i<16;i++)Bp[(h*16+i)*128+j]=0.f;}
        }else{
#pragma unroll
            for(int i=0;i<4;i++){int g=i*1024+t*4;*(float4*)(Bp+g)=*(const float4*)(W+kc*128+g);}
        }
        __syncthreads();
        const float*Ab=At+rg*8;const float*Bb=Bp+cg*4;
#pragma unroll 8
        for(int k=0;k<32;k++){
            ulonglong2 A0=*(const ulonglong2*)(Ab+k*68);
            ulonglong2 A1=*(const ulonglong2*)(Ab+k*68+4);
            float4 b=*(const float4*)(Bb+k*128);
            ull B0=pack2(b.x),B1=pack2(b.y),B2=pack2(b.z),B3=pack2(b.w);
            fma2(acc[0][0],A0.x,B0);fma2(acc[0][1],A0.x,B1);fma2(acc[0][2],A0.x,B2);fma2(acc[0][3],A0.x,B3);
            fma2(acc[1][0],A0.y,B0);fma2(acc[1][1],A0.y,B1);fma2(acc[1][2],A0.y,B2);fma2(acc[1][3],A0.y,B3);
            fma2(acc[2][0],A1.x,B0);fma2(acc[2][1],A1.x,B1);fma2(acc[2][2],A1.x,B2);fma2(acc[2][3],A1.x,B3);
            fma2(acc[3][0],A1.y,B0);fma2(acc[3][1],A1.y,B1);fma2(acc[3][2],A1.y,B2);fma2(acc[3][3],A1.y,B3);
        }
        __syncthreads();
    }
#pragma unroll
    for(int c=0;c<4;c++){
        int j=jt+cg*4+c;if(j>=N)continue;
        float bv=bias?bias[j]:0.f;
#pragma unroll
        for(int p=0;p<4;p++){
            int r=row0+rg*8+2*p;
            float v0=lo32(acc[p][c])+bv,v1=hi32(acc[p][c])+bv;
            if(add){v0+=add[(size_t)r*ldadd+j];v1+=add[(size_t)(r+1)*ldadd+j];}
            if(act){v0=lrelu(v0);v1=lrelu(v1);}
            C[(size_t)r*ldc+j]=v0;C[(size_t)(r+1)*ldc+j]=v1;
        }
    }
}

// ---------------- edge aggregate: rank-1 messages, 1 warp per node ---------
__global__ void k_edge(const int* __restrict__ ei,const int* __restrict__ ea,
                       const float* __restrict__ embBond){
    int w=(blockIdx.x*blockDim.x+threadIdx.x)>>5,lane=threadIdx.x&31;
    if(w>=NN)return;
    int s0=d_off[w],s1=d_off[w+1];
    float4 acc=make_float4(0.f,0.f,0.f,0.f);
    for(int i=s0;i<s1;i++){
        int e=d_csr[i];
        int s=ei[e],a0=ea[2*e],a1=ea[2*e+1];
        float4 hv=*(const float4*)(d_h+(size_t)s*D+lane*4);
        float4 b0=*(const float4*)(embBond+(size_t)a0*D+lane*4);
        float p=hv.x*b0.x+hv.y*b0.y+hv.z*b0.z+hv.w*b0.w;
#pragma unroll
        for(int o=16;o>0;o>>=1)p+=__shfl_xor_sync(~0u,p,o);
        float4 b1=*(const float4*)(embBond+(size_t)a1*D+lane*4);
        acc.x+=p*b1.x;acc.y+=p*b1.y;acc.z+=p*b1.z;acc.w+=p*b1.w;
    }
    float iv=d_invdeg[w];
    acc.x*=iv;acc.y*=iv;acc.z*=iv;acc.w*=iv;
    *(float4*)(d_agg+(size_t)w*D+lane*4)=acc;
}

// ---------------- GRU gates (h update in place) ----------------
__global__ void k_gates(){
    int i=blockIdx.x*blockDim.x+threadIdx.x; // NN*D
    int row=i>>7,c=i&127,b=row*384+c;
    float ir=d_gi[b],iz=d_gi[b+128],in_=d_gi[b+256];
    float hr=d_gh[b],hz=d_gh[b+128],hn=d_gh[b+256];
    float r=1.f/(1.f+expf(-(ir+hr)));
    float z=1.f/(1.f+expf(-(iz+hz)));
    float n=tanhf(in_+r*hn);
    d_h[i]=(1.f-z)*n+z*d_h[i];
}

// ---------------- row gather ----------------
__global__ void k_gather(float* __restrict__ dst,const float* __restrict__ src,
                         const int* __restrict__ idx,int n){
    int t=blockIdx.x*blockDim.x+threadIdx.x;
    int row=t>>5,l=t&31;if(row>=n)return;
    *(float4*)(dst+(size_t)row*128+l*4)=*(const float4*)(src+(size_t)idx[row]*128+l*4);
}

// ---------------- global mean pool (node_batch sorted) ----------------
__global__ void k_pool(const int* __restrict__ nb){
    int g=blockIdx.x,c=threadIdx.x;
    int lo=0,hi=NN;while(lo<hi){int m=(lo+hi)>>1;if(nb[m]<g)lo=m+1;else hi=m;}
    int s=lo;lo=0;hi=NN;while(lo<hi){int m=(lo+hi)>>1;if(nb[m]<=g)lo=m+1;else hi=m;}
    int e=lo;float sum=0.f;
    for(int r=s;r<e;r++)sum+=d_h[(size_t)r*128+c];
    d_gm[g*128+c]=sum/fmaxf((float)(e-s),1.f);
}

// ---------------- stop head: out[g] = g1[g] . w2 + b2 ----------------
__global__ void k_stop(const float* __restrict__ w2,const float* __restrict__ b2,
                       float* __restrict__ out){
    int w=(blockIdx.x*blockDim.x+threadIdx.x)>>5,l=threadIdx.x&31;
    if(w>=NG)return;
    float4 g=*(const float4*)(d_g1+(size_t)w*128+l*4);
    float4 ww=*(const float4*)(w2+l*4);
    float p=g.x*ww.x+g.y*ww.y+g.z*ww.z+g.w*ww.w;
#pragma unroll
    for(int o=16;o>0;o>>=1)p+=__shfl_xor_sync(~0u,p,o);
    if(l==0)out[NS*OPS+w]=p+b2[0];
}

// ---------------- launch ----------------
extern "C" void kernel_launch(void* const* d_in,const int* in_sizes,int n_in,
                              void* d_out,int out_size){
    const int* x   =(const int*)d_in[0];
    const int* st  =(const int*)d_in[1];
    const int* ea  =(const int*)d_in[2];
    const int* ei  =(const int*)d_in[3];
    const int* sni =(const int*)d_in[4];
    const int* nb  =(const int*)d_in[5];
    const float* embB=(const float*)d_in[6];
    const float* embS=(const float*)d_in[7];
    const float* embBond=(const float*)d_in[8];
    const float* b2e_w1=(const float*)d_in[9],  *b2e_b1=(const float*)d_in[10];
    const float* b2e_w2=(const float*)d_in[11], *b2e_b2=(const float*)d_in[12];
    const float* conv_root=(const float*)d_in[13], *conv_bias=(const float*)d_in[14];
    const float* w_ih=(const float*)d_in[15], *w_hh=(const float*)d_in[16];
    const float* b_ih=(const float*)d_in[17], *b_hh=(const float*)d_in[18];
    const float* s2p_w1=(const float*)d_in[19], *s2p_b1=(const float*)d_in[20];
    const float* s2p_w2=(const float*)d_in[21], *s2p_b2=(const float*)d_in[22];
    const float* s2p_w3=(const float*)d_in[23], *s2p_b3=(const float*)d_in[24];
    const float* g2p_w1=(const float*)d_in[25], *g2p_b1=(const float*)d_in[26];
    const float* g2p_w2=(const float*)d_in[27], *g2p_b2=(const float*)d_in[28];
    float* out=(float*)d_out;

    void* p;
    cudaGetSymbolAddress(&p,d_h);   float* ph =(float*)p;
    cudaGetSymbolAddress(&p,d_agg); float* pagg=(float*)p;
    cudaGetSymbolAddress(&p,d_m);   float* pm =(float*)p;
    cudaGetSymbolAddress(&p,d_gi);  float* pgi=(float*)p;
    cudaGetSymbolAddress(&p,d_gh);  float* pgh=(float*)p;
    cudaGetSymbolAddress(&p,d_sg);  float* psg=(float*)p;
    cudaGetSymbolAddress(&p,d_se);  float* pse=(float*)p;
    cudaGetSymbolAddress(&p,d_s1);  float* ps1=(float*)p;
    cudaGetSymbolAddress(&p,d_gm);  float* pgm=(float*)p;
    cudaGetSymbolAddress(&p,d_g1);  float* pg1=(float*)p;

    // CSR build (deterministic after per-node sort)
    k_zero <<<32,256>>>();
    k_count<<<64,256>>>(ei);
    k_scan <<<1,1024>>>();
    k_fill <<<64,256>>>(ei);
    k_sortl<<<32,256>>>();

    // block2emb: h = act(emb_block[x]@w1^T+b1)@w2^T+b2
    k_gather<<<NN*32/256,256>>>(pm,embB,x,NN);
    k_gemm<<<dim3(NN/64,1),256>>>(pm,  b2e_w1,b2e_b1,nullptr,0,pagg,128,128,128,1,1);
    k_gemm<<<dim3(NN/64,1),256>>>(pagg,b2e_w2,b2e_b2,nullptr,0,ph,  128,128,128,1,0);

    for(int s=0;s<NSTEPS;s++){
        k_edge<<<NN/8,256>>>(ei,ea,embBond);
        // m = act(agg + h@root + cb)   (root is direct, not transposed)
        k_gemm<<<dim3(NN/64,1),256>>>(ph,conv_root,conv_bias,pagg,128,pm,128,128,128,0,1);
        k_gemm<<<dim3(NN/64,3),256>>>(pm,w_ih,b_ih,nullptr,0,pgi,384,384,128,1,0);
        k_gemm<<<dim3(NN/64,3),256>>>(ph,w_hh,b_hh,nullptr,0,pgh,384,384,128,1,0);
        k_gates<<<NN*128/256,256>>>();
    }

    // stem head: cat(out[sni], stem_emb) @ w1^T split into two K=128 GEMMs
    k_gather<<<NS*32/256,256>>>(psg,ph,sni,NS);
    k_gather<<<NS*32/256,256>>>(pse,embS,st,NS);
    k_gemm<<<dim3(NS/64,1),256>>>(psg,s2p_w1,    nullptr,nullptr,0,ps1,128,128,256,1,0);
    k_gemm<<<dim3(NS/64,1),256>>>(pse,s2p_w1+128,s2p_b1, ps1,128,  ps1,128,128,256,1,1);
    k_gemm<<<dim3(NS/64,1),256>>>(ps1,s2p_w2,s2p_b2,nullptr,0,pm, 128,128,128,1,1);
    k_gemm<<<dim3(NS/64,1),256>>>(pm, s2p_w3,s2p_b3,nullptr,0,out,105,105,128,1,0);

    // stop head
    k_pool<<<NG,128>>>(nb);
    k_gemm<<<dim3(NG/64,1),256>>>(pgm,g2p_w1,g2p_b1,nullptr,0,pg1,128,128,128,1,1);
    k_stop<<<NG/8,256>>>(g2p_w2,g2p_b2,out);
}

// round 6
// speedup vs baseline: 1.2379x; 1.2379x over previous
#include <cuda_runtime.h>
#include <math.h>

#define D 128
#define NN 8192
#define NE 16384
#define NS 4096
#define NG 256
#define OPS 105
#define NSTEPS 12
#define ATS 68

typedef unsigned long long ull;

// ---------------- scratch (device globals; no runtime allocation) ----------
__device__ float d_h[NN*D], d_h2[NN*D], d_agg[NN*D], d_m[NN*D];
__device__ float d_sg[NS*D], d_se[NS*D], d_s1[NS*D];
__device__ float d_gm[NG*D], d_g1[NG*D];
__device__ int   d_deg[NN], d_off[NN+1], d_cur[NN], d_csr[NE];
__device__ float d_invdeg[NN];

// ---------------- helpers ----------------
__device__ __forceinline__ ull pack2(float x){unsigned u=__float_as_uint(x);ull r;asm("mov.b64 %0,{%1,%1};":"=l"(r):"r"(u));return r;}
__device__ __forceinline__ void fma2(ull&a,ull x,ull y){asm("fma.rn.f32x2 %0,%1,%2,%0;":"+l"(a):"l"(x),"l"(y));}
__device__ __forceinline__ float lo32(ull v){return __uint_as_float((unsigned)v);}
__device__ __forceinline__ float hi32(ull v){return __uint_as_float((unsigned)(v>>32));}
__device__ __forceinline__ float lrelu(float v){return v>0.f?v:0.01f*v;}
__device__ __forceinline__ float sigm(float x){float e=__expf(-x);return __fdividef(1.f,1.f+e);}
__device__ __forceinline__ float tanhfast(float x){
    x=fminf(fmaxf(x,-9.f),9.f);
    float t=__expf(2.f*x);
    return __fdividef(t-1.f,t+1.f);
}

// ---------------- CSR build ----------------
__global__ void k_zero(){int i=blockIdx.x*blockDim.x+threadIdx.x;if(i<NN)d_deg[i]=0;}
__global__ void k_count(const int* __restrict__ ei){int e=blockIdx.x*blockDim.x+threadIdx.x;if(e<NE)atomicAdd(&d_deg[ei[NE+e]],1);}
__global__ void k_scan(){
    __shared__ int ws[32];
    int t=threadIdx.x,base=t*8,v[8],pre[8],s=0;
#pragma unroll
    for(int i=0;i<8;i++){v[i]=d_deg[base+i];pre[i]=s;s+=v[i];}
    int lane=t&31,wid=t>>5,x=s;
#pragma unroll
    for(int o=1;o<32;o<<=1){int y=__shfl_up_sync(~0u,x,o);if(lane>=o)x+=y;}
    if(lane==31)ws[wid]=x;
    __syncthreads();
    if(wid==0){int w=ws[lane],xx=w;
#pragma unroll
        for(int o=1;o<32;o<<=1){int y=__shfl_up_sync(~0u,xx,o);if(lane>=o)xx+=y;}
        ws[lane]=xx-w;}
    __syncthreads();
    int obase=ws[wid]+(x-s);
#pragma unroll
    for(int i=0;i<8;i++){int o=obase+pre[i];d_off[base+i]=o;d_cur[base+i]=o;
        d_invdeg[base+i]=v[i]>0?1.0f/(float)v[i]:0.0f;}
    if(t==1023)d_off[NN]=obase+s;
}
__global__ void k_fill(const int* __restrict__ ei){int e=blockIdx.x*blockDim.x+threadIdx.x;
    if(e<NE){int p=atomicAdd(&d_cur[ei[NE+e]],1);d_csr[p]=e;}}
__global__ void k_sortl(){
    int n=blockIdx.x*blockDim.x+threadIdx.x;if(n>=NN)return;
    int a=d_off[n],b=d_off[n+1];
    for(int i=a+1;i<b;i++){int key=d_csr[i],j=i-1;
        while(j>=a&&d_csr[j]>key){d_csr[j+1]=d_csr[j];j--;}d_csr[j+1]=key;}
}

// ---------------- generic GEMM (prologue/epilogue use) ----------------
__global__ void __launch_bounds__(256)
k_gemm(const float* __restrict__ A,const float* __restrict__ W,
       const float* __restrict__ bias,const float* __restrict__ add,int ldadd,
       float* __restrict__ C,int ldc,int N,int ldw,int transW,int act){
    __shared__ float At[32*ATS];
    __shared__ float Bp[32*128];
    int t=threadIdx.x,rg=t>>5,cg=t&31;
    int row0=blockIdx.x*64,jt=blockIdx.y*128;
    ull acc[4][4];
#pragma unroll
    for(int p=0;p<4;p++)
#pragma unroll
        for(int c=0;c<4;c++)acc[p][c]=0ull;
    for(int kc=0;kc<128;kc+=32){
        { int rl=t&63,kg=t>>6;const float*src=A+(size_t)(row0+rl)*128+kc+kg*8;
          float4 v0=*(const float4*)src,v1=*(const float4*)(src+4);int kb=kg*8;
          At[(kb+0)*ATS+rl]=v0.x;At[(kb+1)*ATS+rl]=v0.y;At[(kb+2)*ATS+rl]=v0.z;At[(kb+3)*ATS+rl]=v0.w;
          At[(kb+4)*ATS+rl]=v1.x;At[(kb+5)*ATS+rl]=v1.y;At[(kb+6)*ATS+rl]=v1.z;At[(kb+7)*ATS+rl]=v1.w;}
        if(transW){
            int j=t>>1,h=t&1;
            if(jt+j<N){const float*src=W+(size_t)(jt+j)*ldw+kc+h*16;
#pragma unroll
                for(int i=0;i<4;i++){float4 v=*(const float4*)(src+i*4);int kk=h*16+i*4;
                    Bp[(kk+0)*128+j]=v.x;Bp[(kk+1)*128+j]=v.y;Bp[(kk+2)*128+j]=v.z;Bp[(kk+3)*128+j]=v.w;}
            }else{
#pragma unroll
                for(int i=0;i<16;i++)Bp[(h*16+i)*128+j]=0.f;}
        }else{
#pragma unroll
            for(int i=0;i<4;i++){int g=i*1024+t*4;*(float4*)(Bp+g)=*(const float4*)(W+kc*128+g);}
        }
        __syncthreads();
        const float*Ab=At+rg*8;const float*Bb=Bp+cg*4;
#pragma unroll 8
        for(int k=0;k<32;k++){
            ulonglong2 A0=*(const ulonglong2*)(Ab+k*ATS);
            ulonglong2 A1=*(const ulonglong2*)(Ab+k*ATS+4);
            float4 b=*(const float4*)(Bb+k*128);
            ull B0=pack2(b.x),B1=pack2(b.y),B2=pack2(b.z),B3=pack2(b.w);
            fma2(acc[0][0],A0.x,B0);fma2(acc[0][1],A0.x,B1);fma2(acc[0][2],A0.x,B2);fma2(acc[0][3],A0.x,B3);
            fma2(acc[1][0],A0.y,B0);fma2(acc[1][1],A0.y,B1);fma2(acc[1][2],A0.y,B2);fma2(acc[1][3],A0.y,B3);
            fma2(acc[2][0],A1.x,B0);fma2(acc[2][1],A1.x,B1);fma2(acc[2][2],A1.x,B2);fma2(acc[2][3],A1.x,B3);
            fma2(acc[3][0],A1.y,B0);fma2(acc[3][1],A1.y,B1);fma2(acc[3][2],A1.y,B2);fma2(acc[3][3],A1.y,B3);
        }
        __syncthreads();
    }
#pragma unroll
    for(int c=0;c<4;c++){
        int j=jt+cg*4+c;if(j>=N)continue;
        float bv=bias?bias[j]:0.f;
#pragma unroll
        for(int p=0;p<4;p++){
            int r=row0+rg*8+2*p;
            float v0=lo32(acc[p][c])+bv,v1=hi32(acc[p][c])+bv;
            if(add){v0+=add[(size_t)r*ldadd+j];v1+=add[(size_t)(r+1)*ldadd+j];}
            if(act){v0=lrelu(v0);v1=lrelu(v1);}
            C[(size_t)r*ldc+j]=v0;C[(size_t)(r+1)*ldc+j]=v1;
        }
    }
}

// ---------------- fused conv step: edge agg + NNConv + GRU, one kernel -----
// grid 128 blocks x 256 thr; 64 rows per block. h double-buffered (hin/hout).
__global__ void __launch_bounds__(256)
k_step(const float* __restrict__ hin, float* __restrict__ hout,
       const int* __restrict__ ei, const int* __restrict__ ea,
       const float* __restrict__ embBond,
       const float* __restrict__ root, const float* __restrict__ cbias,
       const float* __restrict__ wih, const float* __restrict__ whh,
       const float* __restrict__ bih, const float* __restrict__ bhh){
    extern __shared__ float sm[];
    float* At = sm;                 // h tile   [k][r] 128 x ATS
    float* Mt = At + 128*ATS;       // m tile   [k][r]
    float* Ag = Mt + 128*ATS;       // agg then r-gate, [col][r]
    float* Bi = Ag + 128*ATS;       // 32 x 128 panel
    float* Bh = Bi + 32*128;        // 32 x 128 panel
    int t=threadIdx.x,rg=t>>5,cg=t&31,lane=t&31;
    int row0=blockIdx.x*64;

    // --- load h tile transposed ---
    {
        int rl=t&63,kg=t>>6;
        const float* src=hin+(size_t)(row0+rl)*D+kg*32;
#pragma unroll
        for(int i=0;i<8;i++){
            float4 v=*(const float4*)(src+i*4);
            int kk=kg*32+i*4;
            At[(kk+0)*ATS+rl]=v.x;At[(kk+1)*ATS+rl]=v.y;
            At[(kk+2)*ATS+rl]=v.z;At[(kk+3)*ATS+rl]=v.w;
        }
    }
    // --- edge aggregation (rank-1 messages), warp rg -> nodes rg*8..+7 ---
    for(int q=0;q<8;q++){
        int rl=rg*8+q, n=row0+rl;
        int s0=d_off[n],s1=d_off[n+1];
        float4 acc=make_float4(0.f,0.f,0.f,0.f);
        for(int i=s0;i<s1;i++){
            int e=d_csr[i];
            int s=ei[e],a0=ea[2*e],a1=ea[2*e+1];
            float4 hv=*(const float4*)(hin+(size_t)s*D+lane*4);
            float4 b0=*(const float4*)(embBond+(size_t)a0*D+lane*4);
            float p=hv.x*b0.x+hv.y*b0.y+hv.z*b0.z+hv.w*b0.w;
#pragma unroll
            for(int o=16;o>0;o>>=1)p+=__shfl_xor_sync(~0u,p,o);
            float4 b1=*(const float4*)(embBond+(size_t)a1*D+lane*4);
            acc.x+=p*b1.x;acc.y+=p*b1.y;acc.z+=p*b1.z;acc.w+=p*b1.w;
        }
        float iv=d_invdeg[n];
        Ag[(lane*4+0)*ATS+rl]=acc.x*iv;
        Ag[(lane*4+1)*ATS+rl]=acc.y*iv;
        Ag[(lane*4+2)*ATS+rl]=acc.z*iv;
        Ag[(lane*4+3)*ATS+rl]=acc.w*iv;
    }
    __syncthreads();

    // --- conv GEMM: m = lrelu(agg + h @ root + cbias), m kept in smem ---
    {
        ull acc[4][4];
#pragma unroll
        for(int p=0;p<4;p++)
#pragma unroll
            for(int c=0;c<4;c++)acc[p][c]=0ull;
        float4 v[4];
#pragma unroll
        for(int i=0;i<4;i++)v[i]=*(const float4*)(root+i*1024+t*4);  // chunk 0
        for(int kc=0;kc<128;kc+=32){
#pragma unroll
            for(int i=0;i<4;i++)*(float4*)(Bi+i*1024+t*4)=v[i];
            __syncthreads();
            if(kc<96){
#pragma unroll
                for(int i=0;i<4;i++)v[i]=*(const float4*)(root+(kc+32)*128+i*1024+t*4);
            }
            const float*Ab=At+kc*ATS+rg*8;const float*Bb=Bi+cg*4;
#pragma unroll 8
            for(int k=0;k<32;k++){
                ulonglong2 A0=*(const ulonglong2*)(Ab+k*ATS);
                ulonglong2 A1=*(const ulonglong2*)(Ab+k*ATS+4);
                float4 b=*(const float4*)(Bb+k*128);
                ull B0=pack2(b.x),B1=pack2(b.y),B2=pack2(b.z),B3=pack2(b.w);
                fma2(acc[0][0],A0.x,B0);fma2(acc[0][1],A0.x,B1);fma2(acc[0][2],A0.x,B2);fma2(acc[0][3],A0.x,B3);
                fma2(acc[1][0],A0.y,B0);fma2(acc[1][1],A0.y,B1);fma2(acc[1][2],A0.y,B2);fma2(acc[1][3],A0.y,B3);
                fma2(acc[2][0],A1.x,B0);fma2(acc[2][1],A1.x,B1);fma2(acc[2][2],A1.x,B2);fma2(acc[2][3],A1.x,B3);
                fma2(acc[3][0],A1.y,B0);fma2(acc[3][1],A1.y,B1);fma2(acc[3][2],A1.y,B2);fma2(acc[3][3],A1.y,B3);
            }
            __syncthreads();
        }
#pragma unroll
        for(int c=0;c<4;c++){
            int j=cg*4+c;float bv=cbias[j];
#pragma unroll
            for(int p=0;p<4;p++){
                int r=rg*8+2*p;
                float v0=lo32(acc[p][c])+bv+Ag[j*ATS+r];
                float v1=hi32(acc[p][c])+bv+Ag[j*ATS+r+1];
                Mt[j*ATS+r]=lrelu(v0);Mt[j*ATS+r+1]=lrelu(v1);
            }
        }
    }
    __syncthreads();

    // --- GRU: gi = m@wih^T, gh = h@whh^T, gates fused. jt 0=r 1=z 2=n ---
    float zz[4][4][2];
#pragma unroll
    for(int jt=0;jt<3;jt++){
        ull ai[4][4],ah[4][4];
#pragma unroll
        for(int p=0;p<4;p++)
#pragma unroll
            for(int c=0;c<4;c++){ai[p][c]=0ull;ah[p][c]=0ull;}
        int jb=t>>1,hb=t&1;
        float4 vi[4],vh[4];
        {
            const float* si=wih+(size_t)(jt*128+jb)*D+hb*16;
            const float* sh=whh+(size_t)(jt*128+jb)*D+hb*16;
#pragma unroll
            for(int i=0;i<4;i++){vi[i]=*(const float4*)(si+i*4);vh[i]=*(const float4*)(sh+i*4);}
        }
        for(int kc=0;kc<128;kc+=32){
#pragma unroll
            for(int i=0;i<4;i++){
                int kk=hb*16+i*4;
                Bi[(kk+0)*128+jb]=vi[i].x;Bi[(kk+1)*128+jb]=vi[i].y;Bi[(kk+2)*128+jb]=vi[i].z;Bi[(kk+3)*128+jb]=vi[i].w;
                Bh[(kk+0)*128+jb]=vh[i].x;Bh[(kk+1)*128+jb]=vh[i].y;Bh[(kk+2)*128+jb]=vh[i].z;Bh[(kk+3)*128+jb]=vh[i].w;
            }
            __syncthreads();
            if(kc<96){
                const float* si=wih+(size_t)(jt*128+jb)*D+kc+32+hb*16;
                const float* sh=whh+(size_t)(jt*128+jb)*D+kc+32+hb*16;
#pragma unroll
                for(int i=0;i<4;i++){vi[i]=*(const float4*)(si+i*4);vh[i]=*(const float4*)(sh+i*4);}
            }
            const float*Mb=Mt+kc*ATS+rg*8;const float*Ab=At+kc*ATS+rg*8;
            const float*Bib=Bi+cg*4;const float*Bhb=Bh+cg*4;
#pragma unroll 4
            for(int k=0;k<32;k++){
                ulonglong2 M0=*(const ulonglong2*)(Mb+k*ATS);
                ulonglong2 M1=*(const ulonglong2*)(Mb+k*ATS+4);
                ulonglong2 H0=*(const ulonglong2*)(Ab+k*ATS);
                ulonglong2 H1=*(const ulonglong2*)(Ab+k*ATS+4);
                float4 fi=*(const float4*)(Bib+k*128);
                float4 fh=*(const float4*)(Bhb+k*128);
                ull I0=pack2(fi.x),I1=pack2(fi.y),I2=pack2(fi.z),I3=pack2(fi.w);
                ull G0=pack2(fh.x),G1=pack2(fh.y),G2=pack2(fh.z),G3=pack2(fh.w);
                fma2(ai[0][0],M0.x,I0);fma2(ai[0][1],M0.x,I1);fma2(ai[0][2],M0.x,I2);fma2(ai[0][3],M0.x,I3);
                fma2(ai[1][0],M0.y,I0);fma2(ai[1][1],M0.y,I1);fma2(ai[1][2],M0.y,I2);fma2(ai[1][3],M0.y,I3);
                fma2(ai[2][0],M1.x,I0);fma2(ai[2][1],M1.x,I1);fma2(ai[2][2],M1.x,I2);fma2(ai[2][3],M1.x,I3);
                fma2(ai[3][0],M1.y,I0);fma2(ai[3][1],M1.y,I1);fma2(ai[3][2],M1.y,I2);fma2(ai[3][3],M1.y,I3);
                fma2(ah[0][0],H0.x,G0);fma2(ah[0][1],H0.x,G1);fma2(ah[0][2],H0.x,G2);fma2(ah[0][3],H0.x,G3);
                fma2(ah[1][0],H0.y,G0);fma2(ah[1][1],H0.y,G1);fma2(ah[1][2],H0.y,G2);fma2(ah[1][3],H0.y,G3);
                fma2(ah[2][0],H1.x,G0);fma2(ah[2][1],H1.x,G1);fma2(ah[2][2],H1.x,G2);fma2(ah[2][3],H1.x,G3);
                fma2(ah[3][0],H1.y,G0);fma2(ah[3][1],H1.y,G1);fma2(ah[3][2],H1.y,G2);fma2(ah[3][3],H1.y,G3);
            }
            __syncthreads();
        }
        float4 bi4=*(const float4*)(bih+jt*128+cg*4);
        float4 bh4=*(const float4*)(bhh+jt*128+cg*4);
        float biv[4]={bi4.x,bi4.y,bi4.z,bi4.w};
        float bhv[4]={bh4.x,bh4.y,bh4.z,bh4.w};
        if(jt==0){            // r gate -> Ag smem
#pragma unroll
            for(int c=0;c<4;c++){int j=cg*4+c;
#pragma unroll
                for(int p=0;p<4;p++){int r=rg*8+2*p;
                    Ag[j*ATS+r]  =sigm(lo32(ai[p][c])+biv[c]+lo32(ah[p][c])+bhv[c]);
                    Ag[j*ATS+r+1]=sigm(hi32(ai[p][c])+biv[c]+hi32(ah[p][c])+bhv[c]);
                }}
            __syncthreads();
        }else if(jt==1){      // z gate -> regs
#pragma unroll
            for(int c=0;c<4;c++)
#pragma unroll
                for(int p=0;p<4;p++){
                    zz[p][c][0]=sigm(lo32(ai[p][c])+biv[c]+lo32(ah[p][c])+bhv[c]);
                    zz[p][c][1]=sigm(hi32(ai[p][c])+biv[c]+hi32(ah[p][c])+bhv[c]);
                }
        }else{                // n gate + h update
#pragma unroll
            for(int p=0;p<4;p++){
                int r=rg*8+2*p;
                float o0[4],o1[4];
#pragma unroll
                for(int c=0;c<4;c++){
                    int j=cg*4+c;
                    float rr0=Ag[j*ATS+r],rr1=Ag[j*ATS+r+1];
                    float n0=tanhfast(lo32(ai[p][c])+biv[c]+rr0*(lo32(ah[p][c])+bhv[c]));
                    float n1=tanhfast(hi32(ai[p][c])+biv[c]+rr1*(hi32(ah[p][c])+bhv[c]));
                    float h0=At[j*ATS+r],h1=At[j*ATS+r+1];
                    float z0=zz[p][c][0],z1=zz[p][c][1];
                    o0[c]=(1.f-z0)*n0+z0*h0;
                    o1[c]=(1.f-z1)*n1+z1*h1;
                }
                *(float4*)(hout+(size_t)(row0+r)*D+cg*4)  =make_float4(o0[0],o0[1],o0[2],o0[3]);
                *(float4*)(hout+(size_t)(row0+r+1)*D+cg*4)=make_float4(o1[0],o1[1],o1[2],o1[3]);
            }
        }
    }
}

// ---------------- row gather ----------------
__global__ void k_gather(float* __restrict__ dst,const float* __restrict__ src,
                         const int* __restrict__ idx,int n){
    int t=blockIdx.x*blockDim.x+threadIdx.x;
    int row=t>>5,l=t&31;if(row>=n)return;
    *(float4*)(dst+(size_t)row*128+l*4)=*(const float4*)(src+(size_t)idx[row]*128+l*4);
}

// ---------------- global mean pool (node_batch sorted) ----------------
__global__ void k_pool(const int* __restrict__ nb){
    int g=blockIdx.x,c=threadIdx.x;
    int lo=0,hi=NN;while(lo<hi){int m=(lo+hi)>>1;if(nb[m]<g)lo=m+1;else hi=m;}
    int s=lo;lo=0;hi=NN;while(lo<hi){int m=(lo+hi)>>1;if(nb[m]<=g)lo=m+1;else hi=m;}
    int e=lo;float sum=0.f;
    for(int r=s;r<e;r++)sum+=d_h[(size_t)r*128+c];
    d_gm[g*128+c]=sum/fmaxf((float)(e-s),1.f);
}

// ---------------- stop head ----------------
__global__ void k_stop(const float* __restrict__ w2,const float* __restrict__ b2,
                       float* __restrict__ out){
    int w=(blockIdx.x*blockDim.x+threadIdx.x)>>5,l=threadIdx.x&31;
    if(w>=NG)return;
    float4 g=*(const float4*)(d_g1+(size_t)w*128+l*4);
    float4 ww=*(const float4*)(w2+l*4);
    float p=g.x*ww.x+g.y*ww.y+g.z*ww.z+g.w*ww.w;
#pragma unroll
    for(int o=16;o>0;o>>=1)p+=__shfl_xor_sync(~0u,p,o);
    if(l==0)out[NS*OPS+w]=p+b2[0];
}

// ---------------- launch ----------------
extern "C" void kernel_launch(void* const* d_in,const int* in_sizes,int n_in,
                              void* d_out,int out_size){
    const int* x   =(const int*)d_in[0];
    const int* st  =(const int*)d_in[1];
    const int* ea  =(const int*)d_in[2];
    const int* ei  =(const int*)d_in[3];
    const int* sni =(const int*)d_in[4];
    const int* nb  =(const int*)d_in[5];
    const float* embB=(const float*)d_in[6];
    const float* embS=(const float*)d_in[7];
    const float* embBond=(const float*)d_in[8];
    const float* b2e_w1=(const float*)d_in[9],  *b2e_b1=(const float*)d_in[10];
    const float* b2e_w2=(const float*)d_in[11], *b2e_b2=(const float*)d_in[12];
    const float* conv_root=(const float*)d_in[13], *conv_bias=(const float*)d_in[14];
    const float* w_ih=(const float*)d_in[15], *w_hh=(const float*)d_in[16];
    const float* b_ih=(const float*)d_in[17], *b_hh=(const float*)d_in[18];
    const float* s2p_w1=(const float*)d_in[19], *s2p_b1=(const float*)d_in[20];
    const float* s2p_w2=(const float*)d_in[21], *s2p_b2=(const float*)d_in[22];
    const float* s2p_w3=(const float*)d_in[23], *s2p_b3=(const float*)d_in[24];
    const float* g2p_w1=(const float*)d_in[25], *g2p_b1=(const float*)d_in[26];
    const float* g2p_w2=(const float*)d_in[27], *g2p_b2=(const float*)d_in[28];
    float* out=(float*)d_out;

    void* p;
    cudaGetSymbolAddress(&p,d_h);   float* ph =(float*)p;
    cudaGetSymbolAddress(&p,d_h2);  float* ph2=(float*)p;
    cudaGetSymbolAddress(&p,d_agg); float* pagg=(float*)p;
    cudaGetSymbolAddress(&p,d_m);   float* pm =(float*)p;
    cudaGetSymbolAddress(&p,d_sg);  float* psg=(float*)p;
    cudaGetSymbolAddress(&p,d_se);  float* pse=(float*)p;
    cudaGetSymbolAddress(&p,d_s1);  float* ps1=(float*)p;
    cudaGetSymbolAddress(&p,d_gm);  float* pgm=(float*)p;
    cudaGetSymbolAddress(&p,d_g1);  float* pg1=(float*)p;

    const int SMEM=(3*128*ATS+2*32*128)*sizeof(float);   // 137216 B
    static int attr_set=0;
    if(!attr_set){
        cudaFuncSetAttribute(k_step,cudaFuncAttributeMaxDynamicSharedMemorySize,SMEM);
        attr_set=1;
    }

    // CSR build (deterministic after per-node sort)
    k_zero <<<32,256>>>();
    k_count<<<64,256>>>(ei);
    k_scan <<<1,1024>>>();
    k_fill <<<64,256>>>(ei);
    k_sortl<<<32,256>>>();

    // block2emb
    k_gather<<<NN*32/256,256>>>(pm,embB,x,NN);
    k_gemm<<<dim3(NN/64,1),256>>>(pm,  b2e_w1,b2e_b1,nullptr,0,pagg,128,128,128,1,1);
    k_gemm<<<dim3(NN/64,1),256>>>(pagg,b2e_w2,b2e_b2,nullptr,0,ph,  128,128,128,1,0);

    // 12 fused conv steps, h ping-pong (even count -> ends in ph)
    for(int s=0;s<NSTEPS;s++){
        const float* hi=(s&1)?ph2:ph;
        float* ho=(s&1)?ph:ph2;
        k_step<<<128,256,SMEM>>>(hi,ho,ei,ea,embBond,conv_root,conv_bias,
                                 w_ih,w_hh,b_ih,b_hh);
    }

    // stem head
    k_gather<<<NS*32/256,256>>>(psg,ph,sni,NS);
    k_gather<<<NS*32/256,256>>>(pse,embS,st,NS);
    k_gemm<<<dim3(NS/64,1),256>>>(psg,s2p_w1,    nullptr,nullptr,0,ps1,128,128,256,1,0);
    k_gemm<<<dim3(NS/64,1),256>>>(pse,s2p_w1+128,s2p_b1, ps1,128,  ps1,128,128,256,1,1);
    k_gemm<<<dim3(NS/64,1),256>>>(ps1,s2p_w2,s2p_b2,nullptr,0,pm, 128,128,128,1,1);
    k_gemm<<<dim3(NS/64,1),256>>>(pm, s2p_w3,s2p_b3,nullptr,0,out,105,105,128,1,0);

    // stop head
    k_pool<<<NG,128>>>(nb);
    k_gemm<<<dim3(NG/64,1),256>>>(pgm,g2p_w1,g2p_b1,nullptr,0,pg1,128,128,128,1,1);
    k_stop<<<NG/8,256>>>(g2p_w2,g2p_b2,out);
}

// round 8
// speedup vs baseline: 1.8617x; 1.5040x over previous
#include <cuda_runtime.h>
#include <cuda_bf16.h>
#include <math.h>
#include <stdint.h>

#define D 128
#define NN 8192
#define NE 16384
#define NS 4096
#define NG 256
#define OPS 105
#define NSTEPS 12
#define ATS 68

typedef unsigned long long ull;

// ---------------- scratch ----------------
__device__ float d_h[NN*D], d_h2[NN*D], d_agg[NN*D], d_m[NN*D];
__device__ float d_sg[NS*D], d_se[NS*D], d_s1[NS*D];
__device__ float d_gm[NG*D], d_g1[NG*D];
__device__ int   d_deg[NN], d_off[NN+1], d_cur[NN], d_csr[NE];
__device__ float d_invdeg[NN];
// bf16 weight images [tile][n][k], tiles: 0 rootT, 1..3 wih r/z/n, 4..6 whh r/z/n
__device__ __nv_bfloat16 d_bwh[7*16384], d_bwl[7*16384];

// ---------------- helpers ----------------
__device__ __forceinline__ ull pack2(float x){unsigned u=__float_as_uint(x);ull r;asm("mov.b64 %0,{%1,%1};":"=l"(r):"r"(u));return r;}
__device__ __forceinline__ void fma2(ull&a,ull x,ull y){asm("fma.rn.f32x2 %0,%1,%2,%0;":"+l"(a):"l"(x),"l"(y));}
__device__ __forceinline__ float lo32(ull v){return __uint_as_float((unsigned)v);}
__device__ __forceinline__ float hi32(ull v){return __uint_as_float((unsigned)(v>>32));}
__device__ __forceinline__ float lrelu(float v){return v>0.f?v:0.01f*v;}
__device__ __forceinline__ float sigm(float x){float e=__expf(-x);return __fdividef(1.f,1.f+e);}
__device__ __forceinline__ float tanhfast(float x){
    x=fminf(fmaxf(x,-9.f),9.f);
    float t=__expf(2.f*x);
    return __fdividef(t-1.f,t+1.f);
}
__device__ __forceinline__ uint32_t s2u(const void* p){
    uint32_t a; asm("{ .reg .u64 t; cvta.to.shared.u64 t, %1; cvt.u32.u64 %0, t; }":"=r"(a):"l"(p)); return a;
}
// pack two floats as bf16x2 (lo half = first arg)
__device__ __forceinline__ uint32_t pkbf(float a,float b){
    uint32_t r; asm("cvt.rn.bf16x2.f32 %0, %1, %2;":"=r"(r):"f"(b),"f"(a)); return r;
}
__device__ __forceinline__ float upbf(uint32_t u,int slot){
    return __uint_as_float((slot?(u>>16):(u&0xffffu))<<16);
}

#define CP16(s,g)  asm volatile("cp.async.cg.shared.global [%0], [%1], 16;"::"r"(s),"l"(g):"memory")
#define CPCOMMIT() asm volatile("cp.async.commit_group;":::"memory")
#define CPWAIT()   asm volatile("cp.async.wait_group 0;":::"memory")
#define LDSM4(r0,r1,r2,r3,a) asm volatile( \
    "ldmatrix.sync.aligned.m8n8.x4.shared.b16 {%0,%1,%2,%3},[%4];" \
    :"=r"(r0),"=r"(r1),"=r"(r2),"=r"(r3):"r"(a))
#define MMA(dd,aa,b0,b1) asm volatile( \
    "mma.sync.aligned.m16n8k16.row.col.f32.bf16.bf16.f32 {%0,%1,%2,%3},{%4,%5,%6,%7},{%8,%9},{%0,%1,%2,%3};" \
    : "+f"((dd)[0]),"+f"((dd)[1]),"+f"((dd)[2]),"+f"((dd)[3]) \
    : "r"((aa)[0]),"r"((aa)[1]),"r"((aa)[2]),"r"((aa)[3]),"r"(b0),"r"(b1))

// ---------------- CSR build ----------------
__global__ void k_zero(){int i=blockIdx.x*blockDim.x+threadIdx.x;if(i<NN)d_deg[i]=0;}
__global__ void k_count(const int* __restrict__ ei){int e=blockIdx.x*blockDim.x+threadIdx.x;if(e<NE)atomicAdd(&d_deg[ei[NE+e]],1);}
__global__ void k_scan(){
    __shared__ int ws[32];
    int t=threadIdx.x,base=t*8,v[8],pre[8],s=0;
#pragma unroll
    for(int i=0;i<8;i++){v[i]=d_deg[base+i];pre[i]=s;s+=v[i];}
    int lane=t&31,wid=t>>5,x=s;
#pragma unroll
    for(int o=1;o<32;o<<=1){int y=__shfl_up_sync(~0u,x,o);if(lane>=o)x+=y;}
    if(lane==31)ws[wid]=x;
    __syncthreads();
    if(wid==0){int w=ws[lane],xx=w;
#pragma unroll
        for(int o=1;o<32;o<<=1){int y=__shfl_up_sync(~0u,xx,o);if(lane>=o)xx+=y;}
        ws[lane]=xx-w;}
    __syncthreads();
    int obase=ws[wid]+(x-s);
#pragma unroll
    for(int i=0;i<8;i++){int o=obase+pre[i];d_off[base+i]=o;d_cur[base+i]=o;
        d_invdeg[base+i]=v[i]>0?1.0f/(float)v[i]:0.0f;}
    if(t==1023)d_off[NN]=obase+s;
}
__global__ void k_fill(const int* __restrict__ ei){int e=blockIdx.x*blockDim.x+threadIdx.x;
    if(e<NE){int p=atomicAdd(&d_cur[ei[NE+e]],1);d_csr[p]=e;}}
__global__ void k_sortl(){
    int n=blockIdx.x*blockDim.x+threadIdx.x;if(n>=NN)return;
    int a=d_off[n],b=d_off[n+1];
    for(int i=a+1;i<b;i++){int key=d_csr[i],j=i-1;
        while(j>=a&&d_csr[j]>key){d_csr[j+1]=d_csr[j];j--;}d_csr[j+1]=key;}
}

// ---------------- weight prep: plain [n][k] bf16 hi/lo ----------------
__global__ void k_prepw(const float* __restrict__ root,
                        const float* __restrict__ wih,
                        const float* __restrict__ whh){
    int idx=blockIdx.x*blockDim.x+threadIdx.x;
    if(idx>=7*16384)return;
    int t=idx>>14, rem=idx&16383, n=rem>>7, k=rem&127;
    float v;
    if(t==0)      v=root[k*128+n];
    else if(t<4)  v=wih[((t-1)*128+n)*128+k];
    else          v=whh[((t-4)*128+n)*128+k];
    __nv_bfloat16 hi=__float2bfloat16(v);
    __nv_bfloat16 lo=__float2bfloat16(v-__bfloat162float(hi));
    d_bwh[idx]=hi; d_bwl[idx]=lo;
}

// ---------------- generic fp32 GEMM (prologue/heads) ----------------
__global__ void __launch_bounds__(256)
k_gemm(const float* __restrict__ A,const float* __restrict__ W,
       const float* __restrict__ bias,const float* __restrict__ add,int ldadd,
       float* __restrict__ C,int ldc,int N,int ldw,int transW,int act){
    __shared__ float At[32*ATS];
    __shared__ float Bp[32*128];
    int t=threadIdx.x,rg=t>>5,cg=t&31;
    int row0=blockIdx.x*64,jt=blockIdx.y*128;
    ull acc[4][4];
#pragma unroll
    for(int p=0;p<4;p++)
#pragma unroll
        for(int c=0;c<4;c++)acc[p][c]=0ull;
    for(int kc=0;kc<128;kc+=32){
        { int rl=t&63,kg=t>>6;const float*src=A+(size_t)(row0+rl)*128+kc+kg*8;
          float4 v0=*(const float4*)src,v1=*(const float4*)(src+4);int kb=kg*8;
          At[(kb+0)*ATS+rl]=v0.x;At[(kb+1)*ATS+rl]=v0.y;At[(kb+2)*ATS+rl]=v0.z;At[(kb+3)*ATS+rl]=v0.w;
          At[(kb+4)*ATS+rl]=v1.x;At[(kb+5)*ATS+rl]=v1.y;At[(kb+6)*ATS+rl]=v1.z;At[(kb+7)*ATS+rl]=v1.w;}
        if(transW){
            int j=t>>1,h=t&1;
            if(jt+j<N){const float*src=W+(size_t)(jt+j)*ldw+kc+h*16;
#pragma unroll
                for(int i=0;i<4;i++){float4 v=*(const float4*)(src+i*4);int kk=h*16+i*4;
                    Bp[(kk+0)*128+j]=v.x;Bp[(kk+1)*128+j]=v.y;Bp[(kk+2)*128+j]=v.z;Bp[(kk+3)*128+j]=v.w;}
            }else{
#pragma unroll
                for(int i=0;i<16;i++)Bp[(h*16+i)*128+j]=0.f;}
        }else{
#pragma unroll
            for(int i=0;i<4;i++){int g=i*1024+t*4;*(float4*)(Bp+g)=*(const float4*)(W+kc*128+g);}
        }
        __syncthreads();
        const float*Ab=At+rg*8;const float*Bb=Bp+cg*4;
#pragma unroll 8
        for(int k=0;k<32;k++){
            ulonglong2 A0=*(const ulonglong2*)(Ab+k*ATS);
            ulonglong2 A1=*(const ulonglong2*)(Ab+k*ATS+4);
            float4 b=*(const float4*)(Bb+k*128);
            ull B0=pack2(b.x),B1=pack2(b.y),B2=pack2(b.z),B3=pack2(b.w);
            fma2(acc[0][0],A0.x,B0);fma2(acc[0][1],A0.x,B1);fma2(acc[0][2],A0.x,B2);fma2(acc[0][3],A0.x,B3);
            fma2(acc[1][0],A0.y,B0);fma2(acc[1][1],A0.y,B1);fma2(acc[1][2],A0.y,B2);fma2(acc[1][3],A0.y,B3);
            fma2(acc[2][0],A1.x,B0);fma2(acc[2][1],A1.x,B1);fma2(acc[2][2],A1.x,B2);fma2(acc[2][3],A1.x,B3);
            fma2(acc[3][0],A1.y,B0);fma2(acc[3][1],A1.y,B1);fma2(acc[3][2],A1.y,B2);fma2(acc[3][3],A1.y,B3);
        }
        __syncthreads();
    }
#pragma unroll
    for(int c=0;c<4;c++){
        int j=jt+cg*4+c;if(j>=N)continue;
        float bv=bias?bias[j]:0.f;
#pragma unroll
        for(int p=0;p<4;p++){
            int r=row0+rg*8+2*p;
            float v0=lo32(acc[p][c])+bv,v1=hi32(acc[p][c])+bv;
            if(add){v0+=add[(size_t)r*ldadd+j];v1+=add[(size_t)(r+1)*ldadd+j];}
            if(act){v0=lrelu(v0);v1=lrelu(v1);}
            C[(size_t)r*ldc+j]=v0;C[(size_t)(r+1)*ldc+j]=v1;
        }
    }
}

// ---------------- mma.sync fused conv step ----------------
// 128 blocks x 256 thr; 64 rows/block; warps 0-3: ntiles 0-7, warps 4-7: 8-15.
// SMEM byte offsets:
#define SB0H 0
#define SB0L 34816
#define SB1H 69632
#define SB1L 104448
#define SPM  139264     // m exchange [64][132] f32 (33792B) / gate slots (32KB)
#define SBI  173056     // biases 896 f32
#define SMT  176640
#define STRB 272        // B smem row stride bytes (136 bf16)

__device__ __forceinline__ void stageT(uint32_t sH,uint32_t sL,int tile,int tid){
    const char* gh=(const char*)(d_bwh+tile*16384);
    const char* gl=(const char*)(d_bwl+tile*16384);
#pragma unroll
    for(int q=0;q<8;q++){
        int i=tid+q*256, n=i>>4, c=i&15;
        CP16(sH+n*STRB+c*16, gh+n*256+c*16);
        CP16(sL+n*STRB+c*16, gl+n*256+c*16);
    }
    CPCOMMIT();
}

__device__ __forceinline__ void gemm_pass(float acc[8][4],const uint32_t aH[32],const uint32_t aL[32],
                                          uint32_t bh,uint32_t bl,int bt){
#pragma unroll
    for(int kc=0;kc<8;kc++){
#pragma unroll
        for(int jj=0;jj<4;jj++){
            uint32_t h0,h1,h2,h3,l0,l1,l2,l3;
            uint32_t off=jj*4352+kc*32+bt;
            LDSM4(h0,h1,h2,h3,bh+off);
            LDSM4(l0,l1,l2,l3,bl+off);
            MMA(acc[2*jj],  aH+kc*4,h0,h1);
            MMA(acc[2*jj+1],aH+kc*4,h2,h3);
            MMA(acc[2*jj],  aL+kc*4,h0,h1);
            MMA(acc[2*jj+1],aL+kc*4,h2,h3);
            MMA(acc[2*jj],  aH+kc*4,l0,l1);
            MMA(acc[2*jj+1],aH+kc*4,l2,l3);
        }
    }
}
#define ZACC(acc) {_Pragma("unroll") for(int _n=0;_n<8;_n++){_Pragma("unroll") for(int _d=0;_d<4;_d++)(acc)[_n][_d]=0.f;}}

__global__ void __launch_bounds__(256,1)
k_step_mma(const float* __restrict__ hin, float* __restrict__ hout,
           const int* __restrict__ ei, const int* __restrict__ ea,
           const float* __restrict__ embBond,
           const float* __restrict__ cbias,
           const float* __restrict__ bih, const float* __restrict__ bhh){
    extern __shared__ char smem[];
    uint32_t sb=s2u(smem);
    float* Pm=(float*)(smem+SPM);
    float* Pg=(float*)(smem+SPM);
    float* sbias=(float*)(smem+SBI);
    int tid=threadIdx.x, w=tid>>5, lane=tid&31;
    int row0=blockIdx.x*64;
    int wr=w&3, nt0=(w>>2)*8;
    int bt=nt0*2176+((lane>>3)>>1)*2176+(lane&7)*STRB+((lane>>3)&1)*16;

    for(int i=tid;i<384;i+=256){sbias[i]=bih[i];sbias[384+i]=bhh[i];}
    if(tid<128)sbias[768+tid]=cbias[tid];

    stageT(sb+SB0H,sb+SB0L,0,tid);   // rootT

    // ---- h A-fragments (hi/lo) from global ----
    uint32_t hAh[32],hAl[32];
    {
        int ra=row0+16*wr+(lane>>2);
#pragma unroll
        for(int kc=0;kc<8;kc++)
#pragma unroll
        for(int j=0;j<4;j++){
            int row=ra+(j&1)*8;
            int col=kc*16+(j>>1)*8+(lane&3)*2;
            float2 v=*(const float2*)(hin+(size_t)row*128+col);
            uint32_t ph=pkbf(v.x,v.y);
            float r0=upbf(ph,0),r1=upbf(ph,1);
            hAh[kc*4+j]=ph;
            hAl[kc*4+j]=pkbf(v.x-r0,v.y-r1);
        }
    }

    // ---- edge aggregation (8 nodes/warp) -> d_agg ----
#pragma unroll 1
    for(int q=0;q<8;q++){
        int n=row0+8*w+q;
        int s0=d_off[n],s1=d_off[n+1];
        float4 acc=make_float4(0.f,0.f,0.f,0.f);
        for(int i=s0;i<s1;i++){
            int e=d_csr[i];
            int s=ei[e],a0=ea[2*e],a1=ea[2*e+1];
            float4 hv=*(const float4*)(hin+(size_t)s*D+lane*4);
            float4 b0=*(const float4*)(embBond+(size_t)a0*D+lane*4);
            float p=hv.x*b0.x+hv.y*b0.y+hv.z*b0.z+hv.w*b0.w;
#pragma unroll
            for(int o=16;o>0;o>>=1)p+=__shfl_xor_sync(~0u,p,o);
            float4 b1=*(const float4*)(embBond+(size_t)a1*D+lane*4);
            acc.x+=p*b1.x;acc.y+=p*b1.y;acc.z+=p*b1.z;acc.w+=p*b1.w;
        }
        float iv=d_invdeg[n];
        acc.x*=iv;acc.y*=iv;acc.z*=iv;acc.w*=iv;
        *(float4*)(d_agg+(size_t)n*D+lane*4)=acc;
    }

    float acc[8][4];
    // ---- conv: m = lrelu(h@root + agg + cbias) ----
    CPWAIT(); __syncthreads();
    stageT(sb+SB1H,sb+SB1L,1,tid);               // wih_r
    ZACC(acc);
    gemm_pass(acc,hAh,hAl,sb+SB0H,sb+SB0L,bt);
    {
        int rl0=16*wr+(lane>>2);
#pragma unroll
        for(int n=0;n<8;n++){
            int colg=(nt0+n)*8+(lane&3)*2;
            float2 a0=*(const float2*)(d_agg+(size_t)(row0+rl0)*D+colg);
            float2 a1=*(const float2*)(d_agg+(size_t)(row0+rl0+8)*D+colg);
            float b0=sbias[768+colg],b1=sbias[768+colg+1];
            float2 m0=make_float2(lrelu(acc[n][0]+a0.x+b0),lrelu(acc[n][1]+a0.y+b1));
            float2 m1=make_float2(lrelu(acc[n][2]+a1.x+b0),lrelu(acc[n][3]+a1.y+b1));
            *(float2*)(Pm+rl0*132+colg)=m0;
            *(float2*)(Pm+(rl0+8)*132+colg)=m1;
        }
    }
    __syncthreads();
    // ---- m A-fragments from exchange ----
    uint32_t mAh[32],mAl[32];
    {
        int rl=16*wr+(lane>>2);
#pragma unroll
        for(int kc=0;kc<8;kc++)
#pragma unroll
        for(int j=0;j<4;j++){
            int row=rl+(j&1)*8;
            int col=kc*16+(j>>1)*8+(lane&3)*2;
            float2 v=*(const float2*)(Pm+row*132+col);
            uint32_t ph=pkbf(v.x,v.y);
            mAh[kc*4+j]=ph;
            mAl[kc*4+j]=pkbf(v.x-upbf(ph,0),v.y-upbf(ph,1));
        }
    }

    // ---- r gate: acc = m@wih_r + h@whh_r ----
    CPWAIT(); __syncthreads();
    stageT(sb+SB0H,sb+SB0L,4,tid);               // whh_r
    ZACC(acc);
    gemm_pass(acc,mAh,mAl,sb+SB1H,sb+SB1L,bt);
    CPWAIT(); __syncthreads();
    stageT(sb+SB1H,sb+SB1L,6,tid);               // whh_n
    gemm_pass(acc,hAh,hAl,sb+SB0H,sb+SB0L,bt);
#pragma unroll
    for(int n=0;n<8;n++)
#pragma unroll
    for(int dg=0;dg<4;dg++){
        int col=(nt0+n)*8+(lane&3)*2+(dg&1);
        Pg[(n*4+dg)*256+tid]=sigm(acc[n][dg]+sbias[col]+sbias[384+col]);
    }
    // ---- hn: acc = h@whh_n;  P = r*(hn + bhh_n) ----
    CPWAIT(); __syncthreads();
    stageT(sb+SB0H,sb+SB0L,3,tid);               // wih_n
    ZACC(acc);
    gemm_pass(acc,hAh,hAl,sb+SB1H,sb+SB1L,bt);
#pragma unroll
    for(int n=0;n<8;n++)
#pragma unroll
    for(int dg=0;dg<4;dg++){
        int col=(nt0+n)*8+(lane&3)*2+(dg&1);
        int i=(n*4+dg)*256+tid;
        Pg[i]=Pg[i]*(acc[n][dg]+sbias[640+col]);
    }
    // ---- in: acc = m@wih_n;  P = tanh(in + bih_n + P) ----
    CPWAIT(); __syncthreads();
    stageT(sb+SB1H,sb+SB1L,2,tid);               // wih_z
    ZACC(acc);
    gemm_pass(acc,mAh,mAl,sb+SB0H,sb+SB0L,bt);
#pragma unroll
    for(int n=0;n<8;n++)
#pragma unroll
    for(int dg=0;dg<4;dg++){
        int col=(nt0+n)*8+(lane&3)*2+(dg&1);
        int i=(n*4+dg)*256+tid;
        Pg[i]=tanhfast(acc[n][dg]+sbias[256+col]+Pg[i]);
    }
    // ---- z gate + update ----
    CPWAIT(); __syncthreads();
    stageT(sb+SB0H,sb+SB0L,5,tid);               // whh_z
    ZACC(acc);
    gemm_pass(acc,mAh,mAl,sb+SB1H,sb+SB1L,bt);
    CPWAIT(); __syncthreads();
    gemm_pass(acc,hAh,hAl,sb+SB0H,sb+SB0L,bt);
    {
        int rbase=row0+16*wr+(lane>>2);
#pragma unroll
        for(int n=0;n<8;n++){
            int nt=nt0+n, kc=nt>>1;
            float o[4];
#pragma unroll
            for(int dg=0;dg<4;dg++){
                int col=nt*8+(lane&3)*2+(dg&1);
                int j=((nt&1)<<1)|(dg>>1);
                float hv=upbf(hAh[kc*4+j],dg&1)+upbf(hAl[kc*4+j],dg&1);
                float z=sigm(acc[n][dg]+sbias[128+col]+sbias[512+col]);
                float nv=Pg[(n*4+dg)*256+tid];
                o[dg]=(1.f-z)*nv+z*hv;
            }
            int c0=nt*8+(lane&3)*2;
            *(float2*)(hout+(size_t)rbase*D+c0)    =make_float2(o[0],o[1]);
            *(float2*)(hout+(size_t)(rbase+8)*D+c0)=make_float2(o[2],o[3]);
        }
    }
}

// ---------------- row gather ----------------
__global__ void k_gather(float* __restrict__ dst,const float* __restrict__ src,
                         const int* __restrict__ idx,int n){
    int t=blockIdx.x*blockDim.x+threadIdx.x;
    int row=t>>5,l=t&31;if(row>=n)return;
    *(float4*)(dst+(size_t)row*128+l*4)=*(const float4*)(src+(size_t)idx[row]*128+l*4);
}

// ---------------- global mean pool ----------------
__global__ void k_pool(const int* __restrict__ nb){
    int g=blockIdx.x,c=threadIdx.x;
    int lo=0,hi=NN;while(lo<hi){int m=(lo+hi)>>1;if(nb[m]<g)lo=m+1;else hi=m;}
    int s=lo;lo=0;hi=NN;while(lo<hi){int m=(lo+hi)>>1;if(nb[m]<=g)lo=m+1;else hi=m;}
    int e=lo;float sum=0.f;
    for(int r=s;r<e;r++)sum+=d_h[(size_t)r*128+c];
    d_gm[g*128+c]=sum/fmaxf((float)(e-s),1.f);
}

// ---------------- stop head ----------------
__global__ void k_stop(const float* __restrict__ w2,const float* __restrict__ b2,
                       float* __restrict__ out){
    int w=(blockIdx.x*blockDim.x+threadIdx.x)>>5,l=threadIdx.x&31;
    if(w>=NG)return;
    float4 g=*(const float4*)(d_g1+(size_t)w*128+l*4);
    float4 ww=*(const float4*)(w2+l*4);
    float p=g.x*ww.x+g.y*ww.y+g.z*ww.z+g.w*ww.w;
#pragma unroll
    for(int o=16;o>0;o>>=1)p+=__shfl_xor_sync(~0u,p,o);
    if(l==0)out[NS*OPS+w]=p+b2[0];
}

// ---------------- launch ----------------
extern "C" void kernel_launch(void* const* d_in,const int* in_sizes,int n_in,
                              void* d_out,int out_size){
    const int* x   =(const int*)d_in[0];
    const int* st  =(const int*)d_in[1];
    const int* ea  =(const int*)d_in[2];
    const int* ei  =(const int*)d_in[3];
    const int* sni =(const int*)d_in[4];
    const int* nb  =(const int*)d_in[5];
    const float* embB=(const float*)d_in[6];
    const float* embS=(const float*)d_in[7];
    const float* embBond=(const float*)d_in[8];
    const float* b2e_w1=(const float*)d_in[9],  *b2e_b1=(const float*)d_in[10];
    const float* b2e_w2=(const float*)d_in[11], *b2e_b2=(const float*)d_in[12];
    const float* conv_root=(const float*)d_in[13], *conv_bias=(const float*)d_in[14];
    const float* w_ih=(const float*)d_in[15], *w_hh=(const float*)d_in[16];
    const float* b_ih=(const float*)d_in[17], *b_hh=(const float*)d_in[18];
    const float* s2p_w1=(const float*)d_in[19], *s2p_b1=(const float*)d_in[20];
    const float* s2p_w2=(const float*)d_in[21], *s2p_b2=(const float*)d_in[22];
    const float* s2p_w3=(const float*)d_in[23], *s2p_b3=(const float*)d_in[24];
    const float* g2p_w1=(const float*)d_in[25], *g2p_b1=(const float*)d_in[26];
    const float* g2p_w2=(const float*)d_in[27], *g2p_b2=(const float*)d_in[28];
    float* out=(float*)d_out;

    void* p;
    cudaGetSymbolAddress(&p,d_h);   float* ph =(float*)p;
    cudaGetSymbolAddress(&p,d_h2);  float* ph2=(float*)p;
    cudaGetSymbolAddress(&p,d_agg); float* pagg=(float*)p;
    cudaGetSymbolAddress(&p,d_m);   float* pm =(float*)p;
    cudaGetSymbolAddress(&p,d_sg);  float* psg=(float*)p;
    cudaGetSymbolAddress(&p,d_se);  float* pse=(float*)p;
    cudaGetSymbolAddress(&p,d_s1);  float* ps1=(float*)p;
    cudaGetSymbolAddress(&p,d_gm);  float* pgm=(float*)p;
    cudaGetSymbolAddress(&p,d_g1);  float* pg1=(float*)p;

    static int attr_set=0;
    if(!attr_set){
        cudaFuncSetAttribute(k_step_mma,cudaFuncAttributeMaxDynamicSharedMemorySize,SMT);
        attr_set=1;
    }

    // CSR build + weight prep
    k_zero <<<32,256>>>();
    k_count<<<64,256>>>(ei);
    k_scan <<<1,1024>>>();
    k_fill <<<64,256>>>(ei);
    k_sortl<<<32,256>>>();
    k_prepw<<<448,256>>>(conv_root,w_ih,w_hh);

    // block2emb
    k_gather<<<NN*32/256,256>>>(pm,embB,x,NN);
    k_gemm<<<dim3(NN/64,1),256>>>(pm,  b2e_w1,b2e_b1,nullptr,0,pagg,128,128,128,1,1);
    k_gemm<<<dim3(NN/64,1),256>>>(pagg,b2e_w2,b2e_b2,nullptr,0,ph,  128,128,128,1,0);

    // 12 tensor-core (mma.sync) conv steps, ping-pong -> ends in ph
    for(int s=0;s<NSTEPS;s++){
        const float* hi=(s&1)?ph2:ph;
        float* ho=(s&1)?ph:ph2;
        k_step_mma<<<NN/64,256,SMT>>>(hi,ho,ei,ea,embBond,conv_bias,b_ih,b_hh);
    }

    // stem head
    k_gather<<<NS*32/256,256>>>(psg,ph,sni,NS);
    k_gather<<<NS*32/256,256>>>(pse,embS,st,NS);
    k_gemm<<<dim3(NS/64,1),256>>>(psg,s2p_w1,    nullptr,nullptr,0,ps1,128,128,256,1,0);
    k_gemm<<<dim3(NS/64,1),256>>>(pse,s2p_w1+128,s2p_b1, ps1,128,  ps1,128,128,256,1,1);
    k_gemm<<<dim3(NS/64,1),256>>>(ps1,s2p_w2,s2p_b2,nullptr,0,pm, 128,128,128,1,1);
    k_gemm<<<dim3(NS/64,1),256>>>(pm, s2p_w3,s2p_b3,nullptr,0,out,105,105,128,1,0);

    // stop head
    k_pool<<<NG,128>>>(nb);
    k_gemm<<<dim3(NG/64,1),256>>>(pgm,g2p_w1,g2p_b1,nullptr,0,pg1,128,128,128,1,1);
    k_stop<<<NG/8,256>>>(g2p_w2,g2p_b2,out);
}